// round 6
// baseline (speedup 1.0000x reference)
#include <cuda_runtime.h>
#include <cstdint>

#define NPART   100000
#define NFRAMES 500

// Scratch (no allocation allowed): keys, thresholds, runtime constants
// (2^r multipliers + literal 1) that ptxas cannot constant-fold away.
__device__ uint2    g_keys[NFRAMES];
__device__ uint32_t g_thresh[2];
__device__ uint32_t g_rt[5];   // {2^13, 2^26, 2^17, 2^16, 1}

__device__ __forceinline__ uint32_t rotl32(uint32_t x, int r) {
    return __funnelshift_l(x, x, r);  // SHF (alu pipe)
}

// Exact threefry2x32 (setup path).
__device__ __forceinline__ void threefry_plain(uint32_t k0, uint32_t k1,
                                               uint32_t x0, uint32_t x1,
                                               uint32_t &o0, uint32_t &o1) {
    uint32_t ks2 = k0 ^ k1 ^ 0x1BD11BDAu;
    x0 += k0; x1 += k1;
#define RND(r) { x0 += x1; x1 = rotl32(x1, r); x1 ^= x0; }
    RND(13) RND(15) RND(26) RND(6)
    x0 += k1;  x1 += ks2 + 1u;
    RND(17) RND(29) RND(16) RND(24)
    x0 += ks2; x1 += k0 + 2u;
    RND(13) RND(15) RND(26) RND(6)
    x0 += k0;  x1 += k1 + 3u;
    RND(17) RND(29) RND(16) RND(24)
    x0 += k1;  x1 += ks2 + 4u;
    RND(13) RND(15) RND(26) RND(6)
    x0 += ks2; x1 += k0 + 5u;
#undef RND
    o0 = x0; o1 = x1;
}

__device__ __forceinline__ uint32_t thresh_from_prob(float p) {
    float X = p * 8388608.0f;
    uint32_t T = (uint32_t)X;
    if ((float)T < X) T++;
    return T;
}

// jax_threefry_partitionable derivations (verified rel_err = 0).
__global__ void setup_kernel(const int* __restrict__ seed_ptr) {
    int tid = blockIdx.x * blockDim.x + threadIdx.x;
    long long seed = (long long)(*seed_ptr);
    uint32_t k0 = (uint32_t)(((unsigned long long)seed) >> 32);
    uint32_t k1 = (uint32_t)seed;

    uint32_t kp0, kp1, ks0, ks1;
    threefry_plain(k0, k1, 0u, 0u, kp0, kp1);
    threefry_plain(k0, k1, 0u, 1u, ks0, ks1);

    if (tid < NFRAMES) {
        uint32_t o0, o1;
        threefry_plain(ks0, ks1, 0u, (uint32_t)tid, o0, o1);
        g_keys[tid] = make_uint2(o0, o1);
    }
    if (tid == 0) {
        uint32_t o0, o1;
        threefry_plain(kp0, kp1, 0u, 0u, o0, o1);
        uint32_t bits = o0 ^ o1;
        float u = __uint_as_float((bits >> 9) | 0x3f800000u) - 1.0f;
        float p = u * 0.001f;
        g_thresh[0] = thresh_from_prob(0.2f);
        g_thresh[1] = thresh_from_prob(p);
        g_rt[0] = 1u << 13; g_rt[1] = 1u << 26;
        g_rt[2] = 1u << 17; g_rt[3] = 1u << 16;
        g_rt[4] = 1u;
    }
}

// Forced-fma add: mad.lo with runtime multiplier 1 (IMAD, fma pipe).
__device__ __forceinline__ uint32_t madd(uint32_t a, uint32_t one, uint32_t b) {
    uint32_t r;
    asm("mad.lo.u32 %0, %1, %2, %3;" : "=r"(r) : "r"(a), "r"(one), "r"(b));
    return r;
}

// WIDE rotate: x*2^r on fma pipe, then one LOP3 (hi|lo)^x0 on alu (lut 0x56).
__device__ __forceinline__ uint32_t mulrot_xor(uint32_t x, uint32_t pow2r, uint32_t x0) {
    uint64_t w;
    asm("mul.wide.u32 %0, %1, %2;" : "=l"(w) : "r"(x), "r"(pow2r));
    uint32_t lo = (uint32_t)w;
    uint32_t hi = (uint32_t)(w >> 32);
    uint32_t r;
    asm("lop3.b32 %0, %1, %2, %3, 0x56;" : "=r"(r) : "r"(hi), "r"(lo), "r"(x0));
    return r;
}

// Hot path: 2 particles/thread (ILP=2), pipe-balanced 50/50 alu:fma rounds.
__global__ void __launch_bounds__(32)
hmm_kernel(const float* __restrict__ initial, float4* __restrict__ out) {
    int t = blockIdx.x * blockDim.x + threadIdx.x;
    if (t >= NPART / 2) return;

    const uint32_t m13 = g_rt[0], m26 = g_rt[1], m17 = g_rt[2], m16 = g_rt[3];
    const uint32_t one = g_rt[4];
    const uint32_t t0 = g_thresh[0];
    const uint32_t t1 = g_thresh[1];

    const int na = 2 * t;
    uint32_t sa = (initial[2 * na + 1] > 0.5f) ? 1u : 0u;
    uint32_t sb = (initial[2 * na + 3] > 0.5f) ? 1u : 0u;

    const uint32_t ja_base = 4u * (uint32_t)t;
    const uint32_t jb_base = 4u * (uint32_t)t + 2u;

    float4* optr = out + t;

#pragma unroll 2
    for (int f = 0; f < NFRAMES; f++) {
        const uint2 key = __ldg(&g_keys[f]);
        const uint32_t k0 = key.x, k1 = key.y;
        const uint32_t ks2 = k0 ^ k1 ^ 0x1BD11BDAu;

        uint32_t a0 = k0, a1 = (ja_base + sa) + k1;
        uint32_t b0 = k0, b1 = (jb_base + sb) + k1;

        // SHF-form round (alu rotate) — add forced to fma
#define RS(r) { a0 = madd(a1, one, a0); a1 = rotl32(a1, r) ^ a0; \
                b0 = madd(b1, one, b0); b1 = rotl32(b1, r) ^ b0; }
        // WIDE-form round (fma rotate)
#define RW(m) { a0 = madd(a1, one, a0); a1 = mulrot_xor(a1, m, a0); \
                b0 = madd(b1, one, b0); b1 = mulrot_xor(b1, m, b0); }
        // injection: x0-side fma, x1-side alu (IADD3 3-input)
#define INJ(pa, pb, c) { a0 = madd(pa, one, a0); a1 += (pb) + (c); \
                         b0 = madd(pa, one, b0); b1 += (pb) + (c); }

        RW(m13) RS(15) RW(m26) RS(6)
        INJ(k1, ks2, 1u)
        RW(m17) RS(29) RW(m16) RS(24)
        INJ(ks2, k0, 2u)
        RW(m13) RS(15) RW(m26) RS(6)
        INJ(k0, k1, 3u)
        RW(m17) RS(29) RW(m16) RS(24)
        INJ(k1, ks2, 4u)
        RW(m13) RS(15) RW(m26) RS(6)
        INJ(ks2, k0, 5u)
#undef RS
#undef RW
#undef INJ

        uint32_t ma = (a0 ^ a1) >> 9;
        uint32_t mb = (b0 ^ b1) >> 9;
        sa ^= (ma < (sa ? t1 : t0)) ? 1u : 0u;
        sb ^= (mb < (sb ? t1 : t0)) ? 1u : 0u;

        *optr = make_float4(sa ? 0.0f : 1.0f, sa ? 1.0f : 0.0f,
                            sb ? 0.0f : 1.0f, sb ? 1.0f : 0.0f);
        optr += NPART / 2;
    }
}

extern "C" void kernel_launch(void* const* d_in, const int* in_sizes, int n_in,
                              void* d_out, int out_size) {
    const float* initial = (const float*)d_in[0];
    const int*   seed    = (const int*)d_in[1];
    float4*      out     = (float4*)d_out;
    (void)in_sizes; (void)n_in; (void)out_size;

    setup_kernel<<<2, 256>>>(seed);
    int threads_needed = NPART / 2;                 // 50000
    int blocks = (threads_needed + 31) / 32;        // 1563 blocks of 32
    hmm_kernel<<<blocks, 32>>>(initial, out);
}